// round 13
// baseline (speedup 1.0000x reference)
#include <cuda_runtime.h>

// Problem constants (fixed-shape problem)
#define NN   100000
#define EE   3200000
#define HID  64
#define NG   1024
#define NC   21

// Scratch (device globals — no allocations allowed).
__device__ __align__(16) float g_sd  [NN * 2];      // interleaved {agg1, deg} per node
__device__ __align__(16) float g_h1  [NN * HID];    // layer-1 activations
__device__ __align__(16) float g_agg2[NN * HID];    // layer-2 segment sum
__device__ __align__(16) float g_pooled[NG * HID];  // graph pooled sums
__device__ __align__(16) float g_gcnt[NG];          // nodes per graph
__device__ int   g_src  [EE];                       // canonical int32 src
__device__ int   g_dst  [EE];                       // canonical int32 dst
__device__ int   g_batch[NN];                       // canonical int32 batch
__device__ int   g_is64;                            // 1 if inputs are int64

__device__ __forceinline__ int clampi(int v, int hi) {
    return v < 0 ? 0 : (v >= hi ? hi - 1 : v);
}

// ---------------------------------------------------------------------------
// Detect index dtype: if edge_index is int64 (nonneg < 2^31), every high
// 32-bit word is zero. For int32 data those words are node ids (all-zero
// probability ~0). Sample head AND tail windows, both of which lie inside
// the buffer under BOTH dtype interpretations.
// ---------------------------------------------------------------------------
__global__ void k_detect(const unsigned* __restrict__ ei_raw, int e2 /* = 2*E elements */) {
    __shared__ unsigned acc;
    if (threadIdx.x == 0) acc = 0u;
    __syncthreads();
    unsigned v = 0;
    // head: odd words in [0, 8192)
    for (int i = threadIdx.x; i < 4096; i += blockDim.x)
        v |= ei_raw[2 * i + 1];
    // tail: odd words just below e2 (int32 buffer has e2 words, int64 has 2*e2)
    int base = e2 - 4096;
    for (int i = threadIdx.x; i < 2048; i += blockDim.x)
        v |= ei_raw[base + 2 * i + 1];
    atomicOr(&acc, v);
    __syncthreads();
    if (threadIdx.x == 0) g_is64 = (acc == 0u) ? 1 : 0;
}

// ---------------------------------------------------------------------------
// Convert edge_index + batch to canonical int32 under the detected dtype.
// Also zeros all atomically-updated accumulators (fused to save a kernel).
// ---------------------------------------------------------------------------
__global__ void k_convert(const void* __restrict__ ei,
                          const void* __restrict__ bat, int N, int E) {
    int i = blockIdx.x * blockDim.x + threadIdx.x;
    int stride = gridDim.x * blockDim.x;
    if (g_is64) {
        const long long* e64 = (const long long*)ei;
        const long long* b64 = (const long long*)bat;
        for (int j = i; j < E; j += stride) {
            g_src[j] = clampi((int)e64[j], NN);
            g_dst[j] = clampi((int)e64[E + j], NN);
        }
        for (int j = i; j < N; j += stride)
            g_batch[j] = clampi((int)b64[j], NG);
    } else {
        const int* e32 = (const int*)ei;
        const int* b32 = (const int*)bat;
        for (int j = i; j < E; j += stride) {
            g_src[j] = clampi(e32[j], NN);
            g_dst[j] = clampi(e32[E + j], NN);
        }
        for (int j = i; j < N; j += stride)
            g_batch[j] = clampi(b32[j], NG);
    }
    // zero accumulators
    int total = N * HID;
    for (int j = i; j < total; j += stride) g_agg2[j] = 0.0f;
    for (int j = i; j < N * 2; j += stride) g_sd[j] = 0.0f;
    for (int j = i; j < NG * HID; j += stride) g_pooled[j] = 0.0f;
    for (int j = i; j < NG; j += stride) g_gcnt[j] = 0.0f;
}

// ---------------------------------------------------------------------------
// Layer-1 edge pass: one v2 RED adds {x[src], 1.0} into interleaved
// {agg1, deg}[dst].
// ---------------------------------------------------------------------------
__global__ void k_edge1(const float* __restrict__ x, int E) {
    int e = blockIdx.x * blockDim.x + threadIdx.x;
    if (e >= E) return;
    int s = g_src[e];
    int d = g_dst[e];
    float xv = __ldg(&x[s]);
    unsigned long long p = __cvta_generic_to_global(&g_sd[d * 2]);
    asm volatile("red.global.add.v2.f32 [%0], {%1, %2};"
                 :: "l"(p), "f"(xv), "f"(1.0f)
                 : "memory");
}

// ---------------------------------------------------------------------------
// Layer-1 node pass: h1[n,f] = relu(mean1[n]*W1l[f] + x[n]*W1r[f] + b1[f])
// ---------------------------------------------------------------------------
__global__ void k_node1(const float* __restrict__ x,
                        const float* __restrict__ W1l,
                        const float* __restrict__ b1,
                        const float* __restrict__ W1r, int N) {
    int idx = blockIdx.x * blockDim.x + threadIdx.x;
    int n = idx >> 4;
    int c = idx & 15;
    if (n >= N) return;
    float2 sd = ((const float2*)g_sd)[n];
    float mean = sd.x / fmaxf(sd.y, 1.0f);
    float xv = __ldg(&x[n]);
    float4 wl = __ldg(&((const float4*)W1l)[c]);
    float4 bb = __ldg(&((const float4*)b1)[c]);
    float4 wr = __ldg(&((const float4*)W1r)[c]);
    float4 h;
    h.x = fmaxf(fmaf(mean, wl.x, fmaf(xv, wr.x, bb.x)), 0.0f);
    h.y = fmaxf(fmaf(mean, wl.y, fmaf(xv, wr.y, bb.y)), 0.0f);
    h.z = fmaxf(fmaf(mean, wl.z, fmaf(xv, wr.z, bb.z)), 0.0f);
    h.w = fmaxf(fmaf(mean, wl.w, fmaf(xv, wr.w, bb.w)), 0.0f);
    ((float4*)g_h1)[n * 16 + c] = h;
}

// ---------------------------------------------------------------------------
// Layer-2 edge pass: agg2[dst,:] += h1[src,:]. 16 threads/edge, one float4
// each via red.global.add.v4.f32. h1 (25.6MB) is L2-resident.
// ---------------------------------------------------------------------------
__global__ void k_edge2(int E) {
    long long idx = (long long)blockIdx.x * blockDim.x + threadIdx.x;
    int e = (int)(idx >> 4);
    int c = (int)(idx & 15);
    if (e >= E) return;
    int s = g_src[e];
    int d = g_dst[e];
    float4 v = __ldg(&((const float4*)g_h1)[s * 16 + c]);
    unsigned long long p = __cvta_generic_to_global(&g_agg2[d * HID + c * 4]);
    asm volatile("red.global.add.v4.f32 [%0], {%1, %2, %3, %4};"
                 :: "l"(p), "f"(v.x), "f"(v.y), "f"(v.z), "f"(v.w)
                 : "memory");
}

// ---------------------------------------------------------------------------
// Layer-2 node pass fused with graph pooling.
// Each thread: 2 nodes x 4 output features (weight loads reused).
// ---------------------------------------------------------------------------
__global__ void k_node2(const float* __restrict__ W2l,
                        const float* __restrict__ b2,
                        const float* __restrict__ W2r, int N) {
    int idx = blockIdx.x * blockDim.x + threadIdx.x;
    int p = idx >> 4;            // node pair
    int c = idx & 15;            // float4 chunk of output features
    int n0 = 2 * p, n1 = 2 * p + 1;
    if (n0 >= N) return;
    bool has1 = (n1 < N);

    float2 sd0 = ((const float2*)g_sd)[n0];
    float2 sd1 = ((const float2*)g_sd)[has1 ? n1 : 0];
    float inv0 = 1.0f / fmaxf(sd0.y, 1.0f);
    float inv1 = has1 ? (1.0f / fmaxf(sd1.y, 1.0f)) : 0.0f;

    float4 aA0 = make_float4(0.f, 0.f, 0.f, 0.f);
    float4 aA1 = make_float4(0.f, 0.f, 0.f, 0.f);
    float4 aH0 = make_float4(0.f, 0.f, 0.f, 0.f);
    float4 aH1 = make_float4(0.f, 0.f, 0.f, 0.f);

    const float* a0 = &g_agg2[n0 * HID];
    const float* a1 = &g_agg2[has1 ? n1 * HID : 0];
    const float* h0 = &g_h1[n0 * HID];
    const float* h1p = &g_h1[has1 ? n1 * HID : 0];

    #pragma unroll 8
    for (int k = 0; k < HID; k++) {
        float4 wl = __ldg(&((const float4*)W2l)[k * 16 + c]);
        float4 wr = __ldg(&((const float4*)W2r)[k * 16 + c]);
        float av0 = a0[k];
        float hv0 = h0[k];
        aA0.x = fmaf(av0, wl.x, aA0.x); aA0.y = fmaf(av0, wl.y, aA0.y);
        aA0.z = fmaf(av0, wl.z, aA0.z); aA0.w = fmaf(av0, wl.w, aA0.w);
        aH0.x = fmaf(hv0, wr.x, aH0.x); aH0.y = fmaf(hv0, wr.y, aH0.y);
        aH0.z = fmaf(hv0, wr.z, aH0.z); aH0.w = fmaf(hv0, wr.w, aH0.w);
        if (has1) {
            float av1 = a1[k];
            float hv1 = h1p[k];
            aA1.x = fmaf(av1, wl.x, aA1.x); aA1.y = fmaf(av1, wl.y, aA1.y);
            aA1.z = fmaf(av1, wl.z, aA1.z); aA1.w = fmaf(av1, wl.w, aA1.w);
            aH1.x = fmaf(hv1, wr.x, aH1.x); aH1.y = fmaf(hv1, wr.y, aH1.y);
            aH1.z = fmaf(hv1, wr.z, aH1.z); aH1.w = fmaf(hv1, wr.w, aH1.w);
        }
    }

    float4 bb = __ldg(&((const float4*)b2)[c]);

    int b0 = g_batch[n0];
    float* pp0 = &g_pooled[b0 * HID + c * 4];
    atomicAdd(pp0 + 0, fmaxf(fmaf(inv0, aA0.x, aH0.x + bb.x), 0.0f));
    atomicAdd(pp0 + 1, fmaxf(fmaf(inv0, aA0.y, aH0.y + bb.y), 0.0f));
    atomicAdd(pp0 + 2, fmaxf(fmaf(inv0, aA0.z, aH0.z + bb.z), 0.0f));
    atomicAdd(pp0 + 3, fmaxf(fmaf(inv0, aA0.w, aH0.w + bb.w), 0.0f));
    if (has1) {
        int b1i = g_batch[n1];
        float* pp1 = &g_pooled[b1i * HID + c * 4];
        atomicAdd(pp1 + 0, fmaxf(fmaf(inv1, aA1.x, aH1.x + bb.x), 0.0f));
        atomicAdd(pp1 + 1, fmaxf(fmaf(inv1, aA1.y, aH1.y + bb.y), 0.0f));
        atomicAdd(pp1 + 2, fmaxf(fmaf(inv1, aA1.z, aH1.z + bb.z), 0.0f));
        atomicAdd(pp1 + 3, fmaxf(fmaf(inv1, aA1.w, aH1.w + bb.w), 0.0f));
    }
    if (c == 0) {
        atomicAdd(&g_gcnt[b0], 1.0f);
        if (has1) atomicAdd(&g_gcnt[g_batch[n1]], 1.0f);
    }
}

// ---------------------------------------------------------------------------
// Final: out[g,c] = bc[c] + (pooled[g,:]/gcnt[g]) @ Wc[:,c]
// ---------------------------------------------------------------------------
__global__ void k_final(const float* __restrict__ Wc,
                        const float* __restrict__ bc,
                        float* __restrict__ out) {
    int idx = blockIdx.x * blockDim.x + threadIdx.x;
    if (idx >= NG * NC) return;
    int g = idx / NC;
    int c = idx % NC;
    float inv = 1.0f / fmaxf(g_gcnt[g], 1.0f);
    float acc = 0.0f;
    const float* pr = &g_pooled[g * HID];
    #pragma unroll 16
    for (int f = 0; f < HID; f++)
        acc = fmaf(pr[f], __ldg(&Wc[f * NC + c]), acc);
    out[idx] = fmaf(inv, acc, __ldg(&bc[c]));
}

// ---------------------------------------------------------------------------
extern "C" void kernel_launch(void* const* d_in, const int* in_sizes, int n_in,
                              void* d_out, int out_size) {
    const float* x    = (const float*)d_in[0];
    const void*  ei   = d_in[1];
    const void*  bat  = d_in[2];
    const float* W1l  = (const float*)d_in[3];
    const float* b1   = (const float*)d_in[4];
    const float* W1r  = (const float*)d_in[5];
    const float* W2l  = (const float*)d_in[6];
    const float* b2   = (const float*)d_in[7];
    const float* W2r  = (const float*)d_in[8];
    const float* Wc   = (const float*)d_in[9];
    const float* bc   = (const float*)d_in[10];
    float* out = (float*)d_out;

    int N = in_sizes[0];
    int E = in_sizes[1] / 2;

    k_detect<<<1, 256>>>((const unsigned*)ei, in_sizes[1]);
    k_convert<<<1024, 256>>>(ei, bat, N, E);

    k_edge1<<<(E + 255) / 256, 256>>>(x, E);

    k_node1<<<(N * 16 + 255) / 256, 256>>>(x, W1l, b1, W1r, N);

    {
        long long t = (long long)E * 16;
        int blocks = (int)((t + 255) / 256);
        k_edge2<<<blocks, 256>>>(E);
    }

    {
        int pairs = (N + 1) / 2;
        int t = pairs * 16;
        k_node2<<<(t + 255) / 256, 256>>>(W2l, b2, W2r, N);
    }

    k_final<<<(NG * NC + 255) / 256, 256>>>(Wc, bc, out);
}

// round 14
// speedup vs baseline: 1.1234x; 1.1234x over previous
#include <cuda_runtime.h>

// Problem constants (fixed-shape problem)
#define NN   100000
#define EE   3200000
#define HID  64
#define NG   1024
#define NC   21
#define CHUNK 512                      // scan chunk (shift 9)

// Scratch (device globals — no allocations allowed).
__device__ __align__(16) float g_sd  [NN * 2];      // interleaved {agg1, deg} per node
__device__ __align__(16) float g_h1  [NN * HID];    // layer-1 activations
__device__ __align__(16) float g_agg2[NN * HID];    // layer-2 segment sum
__device__ __align__(16) float g_pooled[NG * HID];  // graph pooled sums
__device__ __align__(16) float g_gcnt[NG];          // nodes per graph
__device__ int   g_src  [EE];                       // canonical int32 src
__device__ int   g_dst  [EE];                       // canonical int32 dst
__device__ int   g_batch[NN];                       // canonical int32 batch
__device__ int   g_is64;                            // 1 if inputs are int64
// CSR (by dst)
__device__ int   g_cnt   [NN];                      // in-degree histogram
__device__ int   g_rowptr[NN + 1];
__device__ int   g_cursor[NN];
__device__ int   g_col   [EE];                      // src per CSR slot
__device__ int   g_bsum  [256];                     // scan block sums

__device__ __forceinline__ int clampi(int v, int hi) {
    return v < 0 ? 0 : (v >= hi ? hi - 1 : v);
}

__device__ __forceinline__ int warp_incl_scan(int v, int lane) {
    #pragma unroll
    for (int o = 1; o < 32; o <<= 1) {
        int u = __shfl_up_sync(0xffffffffu, v, o);
        if (lane >= o) v += u;
    }
    return v;
}

// ---------------------------------------------------------------------------
// Detect index dtype (head+tail sampling; both windows in-bounds either way).
// ---------------------------------------------------------------------------
__global__ void k_detect(const unsigned* __restrict__ ei_raw, int e2) {
    __shared__ unsigned acc;
    if (threadIdx.x == 0) acc = 0u;
    __syncthreads();
    unsigned v = 0;
    for (int i = threadIdx.x; i < 4096; i += blockDim.x)
        v |= ei_raw[2 * i + 1];
    int base = e2 - 4096;
    for (int i = threadIdx.x; i < 2048; i += blockDim.x)
        v |= ei_raw[base + 2 * i + 1];
    atomicOr(&acc, v);
    __syncthreads();
    if (threadIdx.x == 0) g_is64 = (acc == 0u) ? 1 : 0;
}

// ---------------------------------------------------------------------------
// Zero histogram + pooled accumulators (must precede the histogram pass).
// ---------------------------------------------------------------------------
__global__ void k_zero(int N) {
    int i = blockIdx.x * blockDim.x + threadIdx.x;
    int stride = gridDim.x * blockDim.x;
    for (int j = i; j < N; j += stride) g_cnt[j] = 0;
    for (int j = i; j < NG * HID; j += stride) g_pooled[j] = 0.0f;
    for (int j = i; j < NG; j += stride) g_gcnt[j] = 0.0f;
}

// ---------------------------------------------------------------------------
// Canonicalize indices to int32 (clamped) + build dst histogram.
// ---------------------------------------------------------------------------
__global__ void k_convert(const void* __restrict__ ei,
                          const void* __restrict__ bat, int N, int E) {
    int i = blockIdx.x * blockDim.x + threadIdx.x;
    int stride = gridDim.x * blockDim.x;
    if (g_is64) {
        const long long* e64 = (const long long*)ei;
        const long long* b64 = (const long long*)bat;
        for (int j = i; j < E; j += stride) {
            int s = clampi((int)e64[j], NN);
            int d = clampi((int)e64[E + j], NN);
            g_src[j] = s;
            g_dst[j] = d;
            atomicAdd(&g_cnt[d], 1);
        }
        for (int j = i; j < N; j += stride)
            g_batch[j] = clampi((int)b64[j], NG);
    } else {
        const int* e32 = (const int*)ei;
        const int* b32 = (const int*)bat;
        for (int j = i; j < E; j += stride) {
            int s = clampi(e32[j], NN);
            int d = clampi(e32[E + j], NN);
            g_src[j] = s;
            g_dst[j] = d;
            atomicAdd(&g_cnt[d], 1);
        }
        for (int j = i; j < N; j += stride)
            g_batch[j] = clampi(b32[j], NG);
    }
}

// ---------------------------------------------------------------------------
// Exclusive scan phase 1: per-chunk (CHUNK=512) local exclusive scan.
// ---------------------------------------------------------------------------
__global__ void k_scan1(int N) {
    int tid = threadIdx.x;
    int i = blockIdx.x * CHUNK + tid;
    int v = (i < N) ? g_cnt[i] : 0;
    int lane = tid & 31, w = tid >> 5;          // 16 warps
    int incl = warp_incl_scan(v, lane);
    __shared__ int ws[16];
    if (lane == 31) ws[w] = incl;
    __syncthreads();
    if (w == 0) {
        int t2 = (lane < 16) ? ws[lane] : 0;
        int i2 = warp_incl_scan(t2, lane);
        if (lane < 16) ws[lane] = i2 - t2;      // exclusive warp offsets
    }
    __syncthreads();
    incl += ws[w];
    if (i < N) g_rowptr[i] = incl - v;          // local exclusive
    if (tid == CHUNK - 1) g_bsum[blockIdx.x] = incl;  // chunk total
}

// ---------------------------------------------------------------------------
// Exclusive scan phase 2: scan the (<=256) chunk totals in one block.
// ---------------------------------------------------------------------------
__global__ void k_scan2(int nblk) {
    int tid = threadIdx.x;                      // 256 threads
    int v = (tid < nblk) ? g_bsum[tid] : 0;
    int lane = tid & 31, w = tid >> 5;          // 8 warps
    int incl = warp_incl_scan(v, lane);
    __shared__ int ws[8];
    if (lane == 31) ws[w] = incl;
    __syncthreads();
    if (w == 0) {
        int t2 = (lane < 8) ? ws[lane] : 0;
        int i2 = warp_incl_scan(t2, lane);
        if (lane < 8) ws[lane] = i2 - t2;
    }
    __syncthreads();
    incl += ws[w];
    if (tid < nblk) g_bsum[tid] = incl - v;     // exclusive chunk offsets
}

// ---------------------------------------------------------------------------
// Exclusive scan phase 3: add chunk offsets; init cursors; rowptr[N]=E.
// ---------------------------------------------------------------------------
__global__ void k_scan3(int N, int E) {
    int i = blockIdx.x * blockDim.x + threadIdx.x;
    if (i < N) {
        int r = g_rowptr[i] + g_bsum[i >> 9];
        g_rowptr[i] = r;
        g_cursor[i] = r;
    }
    if (i == N) g_rowptr[N] = E;
}

// ---------------------------------------------------------------------------
// Fill CSR buckets: col[pos] = src for each edge (pos via per-dst cursor).
// ---------------------------------------------------------------------------
__global__ void k_fill(int E) {
    int e = blockIdx.x * blockDim.x + threadIdx.x;
    if (e >= E) return;
    int d = g_dst[e];
    int pos = atomicAdd(&g_cursor[d], 1);
    g_col[pos] = g_src[e];
}

// ---------------------------------------------------------------------------
// Layer-1 gather: per node, sum x over CSR in-neighbors (no atomics).
// ---------------------------------------------------------------------------
__global__ void k_gather1(const float* __restrict__ x, int N) {
    int n = blockIdx.x * blockDim.x + threadIdx.x;
    if (n >= N) return;
    int beg = g_rowptr[n], end = g_rowptr[n + 1];
    float s = 0.0f;
    int j = beg;
    for (; j + 4 <= end; j += 4) {
        int c0 = g_col[j], c1 = g_col[j + 1], c2 = g_col[j + 2], c3 = g_col[j + 3];
        s += __ldg(&x[c0]) + __ldg(&x[c1]) + __ldg(&x[c2]) + __ldg(&x[c3]);
    }
    for (; j < end; j++) s += __ldg(&x[g_col[j]]);
    ((float2*)g_sd)[n] = make_float2(s, (float)(end - beg));
}

// ---------------------------------------------------------------------------
// Layer-1 node pass: h1[n,f] = relu(mean1[n]*W1l[f] + x[n]*W1r[f] + b1[f])
// ---------------------------------------------------------------------------
__global__ void k_node1(const float* __restrict__ x,
                        const float* __restrict__ W1l,
                        const float* __restrict__ b1,
                        const float* __restrict__ W1r, int N) {
    int idx = blockIdx.x * blockDim.x + threadIdx.x;
    int n = idx >> 4;
    int c = idx & 15;
    if (n >= N) return;
    float2 sd = ((const float2*)g_sd)[n];
    float mean = sd.x / fmaxf(sd.y, 1.0f);
    float xv = __ldg(&x[n]);
    float4 wl = __ldg(&((const float4*)W1l)[c]);
    float4 bb = __ldg(&((const float4*)b1)[c]);
    float4 wr = __ldg(&((const float4*)W1r)[c]);
    float4 h;
    h.x = fmaxf(fmaf(mean, wl.x, fmaf(xv, wr.x, bb.x)), 0.0f);
    h.y = fmaxf(fmaf(mean, wl.y, fmaf(xv, wr.y, bb.y)), 0.0f);
    h.z = fmaxf(fmaf(mean, wl.z, fmaf(xv, wr.z, bb.z)), 0.0f);
    h.w = fmaxf(fmaf(mean, wl.w, fmaf(xv, wr.w, bb.w)), 0.0f);
    ((float4*)g_h1)[n * 16 + c] = h;
}

// ---------------------------------------------------------------------------
// Layer-2 gather: ONE WARP PER NODE. Each lane owns a float2 of the row;
// per edge one coalesced 256B read of h1[src]; agg2 written exactly once.
// Zero atomics, zero pre-zeroing.
// ---------------------------------------------------------------------------
__global__ void k_gather2(int N) {
    int n = (blockIdx.x * blockDim.x + threadIdx.x) >> 5;
    if (n >= N) return;
    int lane = threadIdx.x & 31;
    int beg = g_rowptr[n], end = g_rowptr[n + 1];
    const float2* h1p = (const float2*)g_h1;
    float2 acc = make_float2(0.0f, 0.0f);
    for (int j = beg; j < end; j += 32) {
        int idx = j + lane;
        int myc = (idx < end) ? g_col[idx] : 0;
        int m = end - j;
        if (m > 32) m = 32;
        for (int k = 0; k < m; k++) {
            int s = __shfl_sync(0xffffffffu, myc, k);
            float2 v = __ldg(&h1p[s * 32 + lane]);
            acc.x += v.x;
            acc.y += v.y;
        }
    }
    ((float2*)g_agg2)[n * 32 + lane] = acc;
}

// ---------------------------------------------------------------------------
// Layer-2 node pass fused with graph pooling (unchanged).
// ---------------------------------------------------------------------------
__global__ void k_node2(const float* __restrict__ W2l,
                        const float* __restrict__ b2,
                        const float* __restrict__ W2r, int N) {
    int idx = blockIdx.x * blockDim.x + threadIdx.x;
    int p = idx >> 4;
    int c = idx & 15;
    int n0 = 2 * p, n1 = 2 * p + 1;
    if (n0 >= N) return;
    bool has1 = (n1 < N);

    float2 sd0 = ((const float2*)g_sd)[n0];
    float2 sd1 = ((const float2*)g_sd)[has1 ? n1 : 0];
    float inv0 = 1.0f / fmaxf(sd0.y, 1.0f);
    float inv1 = has1 ? (1.0f / fmaxf(sd1.y, 1.0f)) : 0.0f;

    float4 aA0 = make_float4(0.f, 0.f, 0.f, 0.f);
    float4 aA1 = make_float4(0.f, 0.f, 0.f, 0.f);
    float4 aH0 = make_float4(0.f, 0.f, 0.f, 0.f);
    float4 aH1 = make_float4(0.f, 0.f, 0.f, 0.f);

    const float* a0 = &g_agg2[n0 * HID];
    const float* a1 = &g_agg2[has1 ? n1 * HID : 0];
    const float* h0 = &g_h1[n0 * HID];
    const float* h1p = &g_h1[has1 ? n1 * HID : 0];

    #pragma unroll 8
    for (int k = 0; k < HID; k++) {
        float4 wl = __ldg(&((const float4*)W2l)[k * 16 + c]);
        float4 wr = __ldg(&((const float4*)W2r)[k * 16 + c]);
        float av0 = a0[k];
        float hv0 = h0[k];
        aA0.x = fmaf(av0, wl.x, aA0.x); aA0.y = fmaf(av0, wl.y, aA0.y);
        aA0.z = fmaf(av0, wl.z, aA0.z); aA0.w = fmaf(av0, wl.w, aA0.w);
        aH0.x = fmaf(hv0, wr.x, aH0.x); aH0.y = fmaf(hv0, wr.y, aH0.y);
        aH0.z = fmaf(hv0, wr.z, aH0.z); aH0.w = fmaf(hv0, wr.w, aH0.w);
        if (has1) {
            float av1 = a1[k];
            float hv1 = h1p[k];
            aA1.x = fmaf(av1, wl.x, aA1.x); aA1.y = fmaf(av1, wl.y, aA1.y);
            aA1.z = fmaf(av1, wl.z, aA1.z); aA1.w = fmaf(av1, wl.w, aA1.w);
            aH1.x = fmaf(hv1, wr.x, aH1.x); aH1.y = fmaf(hv1, wr.y, aH1.y);
            aH1.z = fmaf(hv1, wr.z, aH1.z); aH1.w = fmaf(hv1, wr.w, aH1.w);
        }
    }

    float4 bb = __ldg(&((const float4*)b2)[c]);

    int b0 = g_batch[n0];
    float* pp0 = &g_pooled[b0 * HID + c * 4];
    atomicAdd(pp0 + 0, fmaxf(fmaf(inv0, aA0.x, aH0.x + bb.x), 0.0f));
    atomicAdd(pp0 + 1, fmaxf(fmaf(inv0, aA0.y, aH0.y + bb.y), 0.0f));
    atomicAdd(pp0 + 2, fmaxf(fmaf(inv0, aA0.z, aH0.z + bb.z), 0.0f));
    atomicAdd(pp0 + 3, fmaxf(fmaf(inv0, aA0.w, aH0.w + bb.w), 0.0f));
    if (has1) {
        int b1i = g_batch[n1];
        float* pp1 = &g_pooled[b1i * HID + c * 4];
        atomicAdd(pp1 + 0, fmaxf(fmaf(inv1, aA1.x, aH1.x + bb.x), 0.0f));
        atomicAdd(pp1 + 1, fmaxf(fmaf(inv1, aA1.y, aH1.y + bb.y), 0.0f));
        atomicAdd(pp1 + 2, fmaxf(fmaf(inv1, aA1.z, aH1.z + bb.z), 0.0f));
        atomicAdd(pp1 + 3, fmaxf(fmaf(inv1, aA1.w, aH1.w + bb.w), 0.0f));
    }
    if (c == 0) {
        atomicAdd(&g_gcnt[b0], 1.0f);
        if (has1) atomicAdd(&g_gcnt[g_batch[n1]], 1.0f);
    }
}

// ---------------------------------------------------------------------------
// Final: out[g,c] = bc[c] + (pooled[g,:]/gcnt[g]) @ Wc[:,c]
// ---------------------------------------------------------------------------
__global__ void k_final(const float* __restrict__ Wc,
                        const float* __restrict__ bc,
                        float* __restrict__ out) {
    int idx = blockIdx.x * blockDim.x + threadIdx.x;
    if (idx >= NG * NC) return;
    int g = idx / NC;
    int c = idx % NC;
    float inv = 1.0f / fmaxf(g_gcnt[g], 1.0f);
    float acc = 0.0f;
    const float* pr = &g_pooled[g * HID];
    #pragma unroll 16
    for (int f = 0; f < HID; f++)
        acc = fmaf(pr[f], __ldg(&Wc[f * NC + c]), acc);
    out[idx] = fmaf(inv, acc, __ldg(&bc[c]));
}

// ---------------------------------------------------------------------------
extern "C" void kernel_launch(void* const* d_in, const int* in_sizes, int n_in,
                              void* d_out, int out_size) {
    const float* x    = (const float*)d_in[0];
    const void*  ei   = d_in[1];
    const void*  bat  = d_in[2];
    const float* W1l  = (const float*)d_in[3];
    const float* b1   = (const float*)d_in[4];
    const float* W1r  = (const float*)d_in[5];
    const float* W2l  = (const float*)d_in[6];
    const float* b2   = (const float*)d_in[7];
    const float* W2r  = (const float*)d_in[8];
    const float* Wc   = (const float*)d_in[9];
    const float* bc   = (const float*)d_in[10];
    float* out = (float*)d_out;

    int N = in_sizes[0];
    int E = in_sizes[1] / 2;
    int nblk = (N + CHUNK - 1) / CHUNK;   // 196 for N=100000 (<=256 required)

    k_detect<<<1, 256>>>((const unsigned*)ei, in_sizes[1]);
    k_zero<<<256, 256>>>(N);
    k_convert<<<1024, 256>>>(ei, bat, N, E);

    // CSR build
    k_scan1<<<nblk, CHUNK>>>(N);
    k_scan2<<<1, 256>>>(nblk);
    k_scan3<<<(N + 1 + 255) / 256, 256>>>(N, E);
    k_fill<<<(E + 255) / 256, 256>>>(E);

    // Layer 1
    k_gather1<<<(N + 255) / 256, 256>>>(x, N);
    k_node1<<<(N * 16 + 255) / 256, 256>>>(x, W1l, b1, W1r, N);

    // Layer 2
    k_gather2<<<(N * 32 + 255) / 256, 256>>>(N);
    {
        int pairs = (N + 1) / 2;
        int t = pairs * 16;
        k_node2<<<(t + 255) / 256, 256>>>(W2l, b2, W2r, N);
    }

    k_final<<<(NG * NC + 255) / 256, 256>>>(Wc, bc, out);
}

// round 16
// speedup vs baseline: 1.1319x; 1.0076x over previous
#include <cuda_runtime.h>
#include <cuda_fp16.h>

// Problem constants (fixed-shape problem)
#define NN   100000
#define EE   3200000
#define HID  64
#define NG   1024
#define NC   21
#define CHUNK 512                      // scan chunk (shift 9)

// Scratch (device globals — no allocations allowed).
__device__ __align__(16) float   g_sd  [NN * 2];      // {agg1, deg} per node
__device__ __align__(16) float   g_h1  [NN * HID];    // layer-1 activations (fp32)
__device__ __align__(16) __half2 g_h1h [NN * 32];     // fp16 shadow copy for gather2
__device__ __align__(16) float   g_agg2[NN * HID];    // layer-2 segment sum
__device__ __align__(16) float   g_pooled[NG * HID];  // graph pooled sums
__device__ __align__(16) float   g_gcnt[NG];          // nodes per graph
__device__ int   g_src  [EE];
__device__ int   g_dst  [EE];
__device__ int   g_batch[NN];
__device__ int   g_is64;
// CSR (by dst)
__device__ int   g_cnt   [NN];
__device__ int   g_rowptr[NN + 1];
__device__ int   g_cursor[NN];
__device__ int   g_col   [EE];
__device__ int   g_bsum  [256];

__device__ __forceinline__ int clampi(int v, int hi) {
    return v < 0 ? 0 : (v >= hi ? hi - 1 : v);
}

__device__ __forceinline__ int warp_incl_scan(int v, int lane) {
    #pragma unroll
    for (int o = 1; o < 32; o <<= 1) {
        int u = __shfl_up_sync(0xffffffffu, v, o);
        if (lane >= o) v += u;
    }
    return v;
}

// ---------------------------------------------------------------------------
__global__ void k_detect(const unsigned* __restrict__ ei_raw, int e2) {
    __shared__ unsigned acc;
    if (threadIdx.x == 0) acc = 0u;
    __syncthreads();
    unsigned v = 0;
    for (int i = threadIdx.x; i < 4096; i += blockDim.x)
        v |= ei_raw[2 * i + 1];
    int base = e2 - 4096;
    for (int i = threadIdx.x; i < 2048; i += blockDim.x)
        v |= ei_raw[base + 2 * i + 1];
    atomicOr(&acc, v);
    __syncthreads();
    if (threadIdx.x == 0) g_is64 = (acc == 0u) ? 1 : 0;
}

// ---------------------------------------------------------------------------
__global__ void k_zero(int N) {
    int i = blockIdx.x * blockDim.x + threadIdx.x;
    int stride = gridDim.x * blockDim.x;
    for (int j = i; j < N; j += stride) g_cnt[j] = 0;
    for (int j = i; j < NG * HID; j += stride) g_pooled[j] = 0.0f;
    for (int j = i; j < NG; j += stride) g_gcnt[j] = 0.0f;
}

// ---------------------------------------------------------------------------
__global__ void k_convert(const void* __restrict__ ei,
                          const void* __restrict__ bat, int N, int E) {
    int i = blockIdx.x * blockDim.x + threadIdx.x;
    int stride = gridDim.x * blockDim.x;
    if (g_is64) {
        const long long* e64 = (const long long*)ei;
        const long long* b64 = (const long long*)bat;
        for (int j = i; j < E; j += stride) {
            int s = clampi((int)e64[j], NN);
            int d = clampi((int)e64[E + j], NN);
            g_src[j] = s;
            g_dst[j] = d;
            atomicAdd(&g_cnt[d], 1);
        }
        for (int j = i; j < N; j += stride)
            g_batch[j] = clampi((int)b64[j], NG);
    } else {
        const int* e32 = (const int*)ei;
        const int* b32 = (const int*)bat;
        for (int j = i; j < E; j += stride) {
            int s = clampi(e32[j], NN);
            int d = clampi(e32[E + j], NN);
            g_src[j] = s;
            g_dst[j] = d;
            atomicAdd(&g_cnt[d], 1);
        }
        for (int j = i; j < N; j += stride)
            g_batch[j] = clampi(b32[j], NG);
    }
}

// ---------------------------------------------------------------------------
__global__ void k_scan1(int N) {
    int tid = threadIdx.x;
    int i = blockIdx.x * CHUNK + tid;
    int v = (i < N) ? g_cnt[i] : 0;
    int lane = tid & 31, w = tid >> 5;
    int incl = warp_incl_scan(v, lane);
    __shared__ int ws[16];
    if (lane == 31) ws[w] = incl;
    __syncthreads();
    if (w == 0) {
        int t2 = (lane < 16) ? ws[lane] : 0;
        int i2 = warp_incl_scan(t2, lane);
        if (lane < 16) ws[lane] = i2 - t2;
    }
    __syncthreads();
    incl += ws[w];
    if (i < N) g_rowptr[i] = incl - v;
    if (tid == CHUNK - 1) g_bsum[blockIdx.x] = incl;
}

__global__ void k_scan2(int nblk) {
    int tid = threadIdx.x;
    int v = (tid < nblk) ? g_bsum[tid] : 0;
    int lane = tid & 31, w = tid >> 5;
    int incl = warp_incl_scan(v, lane);
    __shared__ int ws[8];
    if (lane == 31) ws[w] = incl;
    __syncthreads();
    if (w == 0) {
        int t2 = (lane < 8) ? ws[lane] : 0;
        int i2 = warp_incl_scan(t2, lane);
        if (lane < 8) ws[lane] = i2 - t2;
    }
    __syncthreads();
    incl += ws[w];
    if (tid < nblk) g_bsum[tid] = incl - v;
}

__global__ void k_scan3(int N, int E) {
    int i = blockIdx.x * blockDim.x + threadIdx.x;
    if (i < N) {
        int r = g_rowptr[i] + g_bsum[i >> 9];
        g_rowptr[i] = r;
        g_cursor[i] = r;
    }
    if (i == N) g_rowptr[N] = E;
}

// ---------------------------------------------------------------------------
__global__ void k_fill(int E) {
    int e = blockIdx.x * blockDim.x + threadIdx.x;
    if (e >= E) return;
    int d = g_dst[e];
    int pos = atomicAdd(&g_cursor[d], 1);
    g_col[pos] = g_src[e];
}

// ---------------------------------------------------------------------------
__global__ void k_gather1(const float* __restrict__ x, int N) {
    int n = blockIdx.x * blockDim.x + threadIdx.x;
    if (n >= N) return;
    int beg = g_rowptr[n], end = g_rowptr[n + 1];
    float s = 0.0f;
    int j = beg;
    for (; j + 4 <= end; j += 4) {
        int c0 = g_col[j], c1 = g_col[j + 1], c2 = g_col[j + 2], c3 = g_col[j + 3];
        s += __ldg(&x[c0]) + __ldg(&x[c1]) + __ldg(&x[c2]) + __ldg(&x[c3]);
    }
    for (; j < end; j++) s += __ldg(&x[g_col[j]]);
    ((float2*)g_sd)[n] = make_float2(s, (float)(end - beg));
}

// ---------------------------------------------------------------------------
// Layer-1 node pass: writes fp32 h1 (for node2 root term) AND fp16 shadow
// copy (for gather2's bandwidth-dominant neighbor reads).
// ---------------------------------------------------------------------------
__global__ void k_node1(const float* __restrict__ x,
                        const float* __restrict__ W1l,
                        const float* __restrict__ b1,
                        const float* __restrict__ W1r, int N) {
    int idx = blockIdx.x * blockDim.x + threadIdx.x;
    int n = idx >> 4;
    int c = idx & 15;
    if (n >= N) return;
    float2 sd = ((const float2*)g_sd)[n];
    float mean = sd.x / fmaxf(sd.y, 1.0f);
    float xv = __ldg(&x[n]);
    float4 wl = __ldg(&((const float4*)W1l)[c]);
    float4 bb = __ldg(&((const float4*)b1)[c]);
    float4 wr = __ldg(&((const float4*)W1r)[c]);
    float4 h;
    h.x = fmaxf(fmaf(mean, wl.x, fmaf(xv, wr.x, bb.x)), 0.0f);
    h.y = fmaxf(fmaf(mean, wl.y, fmaf(xv, wr.y, bb.y)), 0.0f);
    h.z = fmaxf(fmaf(mean, wl.z, fmaf(xv, wr.z, bb.z)), 0.0f);
    h.w = fmaxf(fmaf(mean, wl.w, fmaf(xv, wr.w, bb.w)), 0.0f);
    ((float4*)g_h1)[n * 16 + c] = h;
    g_h1h[n * 32 + c * 2 + 0] = __floats2half2_rn(h.x, h.y);
    g_h1h[n * 32 + c * 2 + 1] = __floats2half2_rn(h.z, h.w);
}

// ---------------------------------------------------------------------------
// Layer-2 gather: ONE WARP PER NODE, fp16 neighbor reads (128B/edge,
// coalesced), fp32 accumulation, agg2 written exactly once. No atomics.
// ---------------------------------------------------------------------------
__global__ void k_gather2(int N) {
    int n = (blockIdx.x * blockDim.x + threadIdx.x) >> 5;
    if (n >= N) return;
    int lane = threadIdx.x & 31;
    int beg = g_rowptr[n], end = g_rowptr[n + 1];
    float2 acc = make_float2(0.0f, 0.0f);
    for (int j = beg; j < end; j += 32) {
        int idx = j + lane;
        int myc = (idx < end) ? g_col[idx] : 0;
        int m = end - j;
        if (m > 32) m = 32;
        for (int k = 0; k < m; k++) {
            int s = __shfl_sync(0xffffffffu, myc, k);
            float2 v = __half22float2(__ldg(&g_h1h[s * 32 + lane]));
            acc.x += v.x;
            acc.y += v.y;
        }
    }
    ((float2*)g_agg2)[n * 32 + lane] = acc;
}

// ---------------------------------------------------------------------------
// Layer-2 node pass fused with graph pooling (root term reads fp32 h1).
// ---------------------------------------------------------------------------
__global__ void k_node2(const float* __restrict__ W2l,
                        const float* __restrict__ b2,
                        const float* __restrict__ W2r, int N) {
    int idx = blockIdx.x * blockDim.x + threadIdx.x;
    int p = idx >> 4;
    int c = idx & 15;
    int n0 = 2 * p, n1 = 2 * p + 1;
    if (n0 >= N) return;
    bool has1 = (n1 < N);

    float2 sd0 = ((const float2*)g_sd)[n0];
    float2 sd1 = ((const float2*)g_sd)[has1 ? n1 : 0];
    float inv0 = 1.0f / fmaxf(sd0.y, 1.0f);
    float inv1 = has1 ? (1.0f / fmaxf(sd1.y, 1.0f)) : 0.0f;

    float4 aA0 = make_float4(0.f, 0.f, 0.f, 0.f);
    float4 aA1 = make_float4(0.f, 0.f, 0.f, 0.f);
    float4 aH0 = make_float4(0.f, 0.f, 0.f, 0.f);
    float4 aH1 = make_float4(0.f, 0.f, 0.f, 0.f);

    const float* a0 = &g_agg2[n0 * HID];
    const float* a1 = &g_agg2[has1 ? n1 * HID : 0];
    const float* h0 = &g_h1[n0 * HID];
    const float* h1p = &g_h1[has1 ? n1 * HID : 0];

    #pragma unroll 8
    for (int k = 0; k < HID; k++) {
        float4 wl = __ldg(&((const float4*)W2l)[k * 16 + c]);
        float4 wr = __ldg(&((const float4*)W2r)[k * 16 + c]);
        float av0 = a0[k];
        float hv0 = h0[k];
        aA0.x = fmaf(av0, wl.x, aA0.x); aA0.y = fmaf(av0, wl.y, aA0.y);
        aA0.z = fmaf(av0, wl.z, aA0.z); aA0.w = fmaf(av0, wl.w, aA0.w);
        aH0.x = fmaf(hv0, wr.x, aH0.x); aH0.y = fmaf(hv0, wr.y, aH0.y);
        aH0.z = fmaf(hv0, wr.z, aH0.z); aH0.w = fmaf(hv0, wr.w, aH0.w);
        if (has1) {
            float av1 = a1[k];
            float hv1 = h1p[k];
            aA1.x = fmaf(av1, wl.x, aA1.x); aA1.y = fmaf(av1, wl.y, aA1.y);
            aA1.z = fmaf(av1, wl.z, aA1.z); aA1.w = fmaf(av1, wl.w, aA1.w);
            aH1.x = fmaf(hv1, wr.x, aH1.x); aH1.y = fmaf(hv1, wr.y, aH1.y);
            aH1.z = fmaf(hv1, wr.z, aH1.z); aH1.w = fmaf(hv1, wr.w, aH1.w);
        }
    }

    float4 bb = __ldg(&((const float4*)b2)[c]);

    int b0 = g_batch[n0];
    float* pp0 = &g_pooled[b0 * HID + c * 4];
    atomicAdd(pp0 + 0, fmaxf(fmaf(inv0, aA0.x, aH0.x + bb.x), 0.0f));
    atomicAdd(pp0 + 1, fmaxf(fmaf(inv0, aA0.y, aH0.y + bb.y), 0.0f));
    atomicAdd(pp0 + 2, fmaxf(fmaf(inv0, aA0.z, aH0.z + bb.z), 0.0f));
    atomicAdd(pp0 + 3, fmaxf(fmaf(inv0, aA0.w, aH0.w + bb.w), 0.0f));
    if (has1) {
        int b1i = g_batch[n1];
        float* pp1 = &g_pooled[b1i * HID + c * 4];
        atomicAdd(pp1 + 0, fmaxf(fmaf(inv1, aA1.x, aH1.x + bb.x), 0.0f));
        atomicAdd(pp1 + 1, fmaxf(fmaf(inv1, aA1.y, aH1.y + bb.y), 0.0f));
        atomicAdd(pp1 + 2, fmaxf(fmaf(inv1, aA1.z, aH1.z + bb.z), 0.0f));
        atomicAdd(pp1 + 3, fmaxf(fmaf(inv1, aA1.w, aH1.w + bb.w), 0.0f));
    }
    if (c == 0) {
        atomicAdd(&g_gcnt[b0], 1.0f);
        if (has1) atomicAdd(&g_gcnt[g_batch[n1]], 1.0f);
    }
}

// ---------------------------------------------------------------------------
__global__ void k_final(const float* __restrict__ Wc,
                        const float* __restrict__ bc,
                        float* __restrict__ out) {
    int idx = blockIdx.x * blockDim.x + threadIdx.x;
    if (idx >= NG * NC) return;
    int g = idx / NC;
    int c = idx % NC;
    float inv = 1.0f / fmaxf(g_gcnt[g], 1.0f);
    float acc = 0.0f;
    const float* pr = &g_pooled[g * HID];
    #pragma unroll 16
    for (int f = 0; f < HID; f++)
        acc = fmaf(pr[f], __ldg(&Wc[f * NC + c]), acc);
    out[idx] = fmaf(inv, acc, __ldg(&bc[c]));
}

// ---------------------------------------------------------------------------
extern "C" void kernel_launch(void* const* d_in, const int* in_sizes, int n_in,
                              void* d_out, int out_size) {
    const float* x    = (const float*)d_in[0];
    const void*  ei   = d_in[1];
    const void*  bat  = d_in[2];
    const float* W1l  = (const float*)d_in[3];
    const float* b1   = (const float*)d_in[4];
    const float* W1r  = (const float*)d_in[5];
    const float* W2l  = (const float*)d_in[6];
    const float* b2   = (const float*)d_in[7];
    const float* W2r  = (const float*)d_in[8];
    const float* Wc   = (const float*)d_in[9];
    const float* bc   = (const float*)d_in[10];
    float* out = (float*)d_out;

    int N = in_sizes[0];
    int E = in_sizes[1] / 2;
    int nblk = (N + CHUNK - 1) / CHUNK;

    k_detect<<<1, 256>>>((const unsigned*)ei, in_sizes[1]);
    k_zero<<<256, 256>>>(N);
    k_convert<<<1024, 256>>>(ei, bat, N, E);

    // CSR build
    k_scan1<<<nblk, CHUNK>>>(N);
    k_scan2<<<1, 256>>>(nblk);
    k_scan3<<<(N + 1 + 255) / 256, 256>>>(N, E);
    k_fill<<<(E + 255) / 256, 256>>>(E);

    // Layer 1
    k_gather1<<<(N + 255) / 256, 256>>>(x, N);
    k_node1<<<(N * 16 + 255) / 256, 256>>>(x, W1l, b1, W1r, N);

    // Layer 2
    k_gather2<<<(N * 32 + 255) / 256, 256>>>(N);
    {
        int pairs = (N + 1) / 2;
        int t = pairs * 16;
        k_node2<<<(t + 255) / 256, 256>>>(W2l, b2, W2r, N);
    }

    k_final<<<(NG * NC + 255) / 256, 256>>>(Wc, bc, out);
}